// round 4
// baseline (speedup 1.0000x reference)
#include <cuda_runtime.h>
#include <math.h>

#define BN   4
#define SEQ  1024
#define CH   768
#define NH   12
#define HD   64
#define ROWS (BN*SEQ)
#define QKVC (3*CH)
#define BH   (BN*NH)
#define BETA 0.2f
#define SCALE 0.125f
#define LN_EPS 1e-5f

__device__ float g_xn[(size_t)ROWS * CH];
__device__ float g_qkv[(size_t)ROWS * QKVC];
__device__ float g_S[(size_t)BH * SEQ * SEQ];

__device__ __forceinline__ float to_tf32(float x) {
    unsigned u;
    asm("cvt.rna.tf32.f32 %0, %1;" : "=r"(u) : "f"(x));
    return __uint_as_float(u);
}
__device__ __forceinline__ void mma8(float* c, const float* a, const float* b) {
    asm volatile(
        "mma.sync.aligned.m16n8k8.row.col.f32.tf32.tf32.f32 "
        "{%0,%1,%2,%3}, {%4,%5,%6,%7}, {%8,%9}, {%0,%1,%2,%3};"
        : "+f"(c[0]), "+f"(c[1]), "+f"(c[2]), "+f"(c[3])
        : "r"(__float_as_uint(a[0])), "r"(__float_as_uint(a[1])),
          "r"(__float_as_uint(a[2])), "r"(__float_as_uint(a[3])),
          "r"(__float_as_uint(b[0])), "r"(__float_as_uint(b[1])));
}

/* ================= LayerNorm: one block per token ================= */
__global__ void ln_kernel(const float* __restrict__ x,
                          const float* __restrict__ gamma,
                          const float* __restrict__ beta) {
    int row = blockIdx.x;
    const float* xr = x + (size_t)row * CH;
    float*       orow = g_xn + (size_t)row * CH;
    int t = threadIdx.x;

    float v0 = xr[t], v1 = xr[t + 256], v2 = xr[t + 512];
    float s  = v0 + v1 + v2;
    float sq = v0 * v0 + v1 * v1 + v2 * v2;

    __shared__ float redS[8], redQ[8], stats[2];
    #pragma unroll
    for (int o = 16; o; o >>= 1) {
        s  += __shfl_down_sync(0xffffffffu, s,  o);
        sq += __shfl_down_sync(0xffffffffu, sq, o);
    }
    int w = t >> 5, l = t & 31;
    if (l == 0) { redS[w] = s; redQ[w] = sq; }
    __syncthreads();
    if (t == 0) {
        float S = 0.f, Q = 0.f;
        #pragma unroll
        for (int i = 0; i < 8; i++) { S += redS[i]; Q += redQ[i]; }
        float mu  = S * (1.0f / CH);
        float var = Q * (1.0f / CH) - mu * mu;
        stats[0] = mu;
        stats[1] = rsqrtf(var + LN_EPS);
    }
    __syncthreads();
    float mu = stats[0], rs = stats[1];
    orow[t]       = (v0 - mu) * rs * gamma[t]       + beta[t];
    orow[t + 256] = (v1 - mu) * rs * gamma[t + 256] + beta[t + 256];
    orow[t + 512] = (v2 - mu) * rs * gamma[t + 512] + beta[t + 512];
}

/* ========== QKV GEMM (tf32 MMA) ========== */
__global__ void qkv_gemm(const float* __restrict__ W,
                         const float* __restrict__ bias) {
    __shared__ float As[128][20];
    __shared__ float Bs[64][20];
    int m0 = blockIdx.y * 128, n0 = blockIdx.x * 64;
    int t = threadIdx.x;
    int warp = t >> 5, lane = t & 31, lr = lane >> 2, lc = lane & 3;
    int wm = (warp >> 1) * 32, wn = (warp & 1) * 32;
    int r = t >> 2, c4 = (t & 3) * 4;

    float acc[2][4][4] = {};
    for (int k0 = 0; k0 < CH; k0 += 16) {
        float4 a0 = *(const float4*)(g_xn + (size_t)(m0 + r) * CH + k0 + c4);
        float4 a1 = *(const float4*)(g_xn + (size_t)(m0 + r + 64) * CH + k0 + c4);
        float4 bb = *(const float4*)(W    + (size_t)(n0 + r) * CH + k0 + c4);
        As[r][c4+0]=to_tf32(a0.x); As[r][c4+1]=to_tf32(a0.y); As[r][c4+2]=to_tf32(a0.z); As[r][c4+3]=to_tf32(a0.w);
        As[r+64][c4+0]=to_tf32(a1.x); As[r+64][c4+1]=to_tf32(a1.y); As[r+64][c4+2]=to_tf32(a1.z); As[r+64][c4+3]=to_tf32(a1.w);
        Bs[r][c4+0]=to_tf32(bb.x); Bs[r][c4+1]=to_tf32(bb.y); Bs[r][c4+2]=to_tf32(bb.z); Bs[r][c4+3]=to_tf32(bb.w);
        __syncthreads();
        #pragma unroll
        for (int kc = 0; kc < 2; kc++) {
            int kb = kc * 8;
            float a[2][4], b[4][2];
            #pragma unroll
            for (int mi = 0; mi < 2; mi++) {
                a[mi][0] = As[wm + mi*16 + lr    ][kb + lc];
                a[mi][1] = As[wm + mi*16 + lr + 8][kb + lc];
                a[mi][2] = As[wm + mi*16 + lr    ][kb + lc + 4];
                a[mi][3] = As[wm + mi*16 + lr + 8][kb + lc + 4];
            }
            #pragma unroll
            for (int ni = 0; ni < 4; ni++) {
                b[ni][0] = Bs[wn + ni*8 + lr][kb + lc];
                b[ni][1] = Bs[wn + ni*8 + lr][kb + lc + 4];
            }
            #pragma unroll
            for (int mi = 0; mi < 2; mi++)
                #pragma unroll
                for (int ni = 0; ni < 4; ni++)
                    mma8(acc[mi][ni], a[mi], b[ni]);
        }
        __syncthreads();
    }
    #pragma unroll
    for (int mi = 0; mi < 2; mi++)
        #pragma unroll
        for (int ni = 0; ni < 4; ni++) {
            int row = m0 + wm + mi*16 + lr;
            int col = n0 + wn + ni*8 + lc*2;
            g_qkv[(size_t)row * QKVC + col    ] = acc[mi][ni][0] + bias[col];
            g_qkv[(size_t)row * QKVC + col + 1] = acc[mi][ni][1] + bias[col+1];
            g_qkv[(size_t)(row+8) * QKVC + col    ] = acc[mi][ni][2] + bias[col];
            g_qkv[(size_t)(row+8) * QKVC + col + 1] = acc[mi][ni][3] + bias[col+1];
        }
}

/* ========== Scores (tf32 MMA) ========== */
__global__ void score_gemm() {
    int bh = blockIdx.z, b = bh / NH, h = bh % NH;
    const float* Q = g_qkv + (size_t)b * SEQ * QKVC + h * HD;
    const float* K = g_qkv + (size_t)b * SEQ * QKVC + CH + h * HD;
    float* S = g_S + (size_t)bh * SEQ * SEQ;

    __shared__ float As[128][20];
    __shared__ float Bs[64][20];
    int m0 = blockIdx.y * 128, n0 = blockIdx.x * 64;
    int t = threadIdx.x;
    int warp = t >> 5, lane = t & 31, lr = lane >> 2, lc = lane & 3;
    int wm = (warp >> 1) * 32, wn = (warp & 1) * 32;
    int r = t >> 2, c4 = (t & 3) * 4;

    float acc[2][4][4] = {};
    for (int k0 = 0; k0 < HD; k0 += 16) {
        float4 a0 = *(const float4*)(Q + (size_t)(m0 + r) * QKVC + k0 + c4);
        float4 a1 = *(const float4*)(Q + (size_t)(m0 + r + 64) * QKVC + k0 + c4);
        float4 bb = *(const float4*)(K + (size_t)(n0 + r) * QKVC + k0 + c4);
        As[r][c4+0]=to_tf32(a0.x); As[r][c4+1]=to_tf32(a0.y); As[r][c4+2]=to_tf32(a0.z); As[r][c4+3]=to_tf32(a0.w);
        As[r+64][c4+0]=to_tf32(a1.x); As[r+64][c4+1]=to_tf32(a1.y); As[r+64][c4+2]=to_tf32(a1.z); As[r+64][c4+3]=to_tf32(a1.w);
        Bs[r][c4+0]=to_tf32(bb.x); Bs[r][c4+1]=to_tf32(bb.y); Bs[r][c4+2]=to_tf32(bb.z); Bs[r][c4+3]=to_tf32(bb.w);
        __syncthreads();
        #pragma unroll
        for (int kc = 0; kc < 2; kc++) {
            int kb = kc * 8;
            float a[2][4], b[4][2];
            #pragma unroll
            for (int mi = 0; mi < 2; mi++) {
                a[mi][0] = As[wm + mi*16 + lr    ][kb + lc];
                a[mi][1] = As[wm + mi*16 + lr + 8][kb + lc];
                a[mi][2] = As[wm + mi*16 + lr    ][kb + lc + 4];
                a[mi][3] = As[wm + mi*16 + lr + 8][kb + lc + 4];
            }
            #pragma unroll
            for (int ni = 0; ni < 4; ni++) {
                b[ni][0] = Bs[wn + ni*8 + lr][kb + lc];
                b[ni][1] = Bs[wn + ni*8 + lr][kb + lc + 4];
            }
            #pragma unroll
            for (int mi = 0; mi < 2; mi++)
                #pragma unroll
                for (int ni = 0; ni < 4; ni++)
                    mma8(acc[mi][ni], a[mi], b[ni]);
        }
        __syncthreads();
    }
    #pragma unroll
    for (int mi = 0; mi < 2; mi++)
        #pragma unroll
        for (int ni = 0; ni < 4; ni++) {
            int row = m0 + wm + mi*16 + lr;
            int col = n0 + wn + ni*8 + lc*2;
            S[(size_t)row * SEQ + col    ] = acc[mi][ni][0] * SCALE;
            S[(size_t)row * SEQ + col + 1] = acc[mi][ni][1] * SCALE;
            S[(size_t)(row+8) * SEQ + col    ] = acc[mi][ni][2] * SCALE;
            S[(size_t)(row+8) * SEQ + col + 1] = acc[mi][ni][3] * SCALE;
        }
}

/* ========= Fused conv + online softmax + PV (flash-style) ========= */
/* CTA = 64 query rows of one (b,h); stream 8 j-tiles of 128 cols.    */
#define BM 64
#define BJ 128
#define V3_STR 132
#define PS_STR 132
#define VS_STR 72

__global__ __launch_bounds__(256) void fused_tail(float* __restrict__ out) {
    int bh = blockIdx.y, b = bh / NH, h = bh % NH;
    int m0 = blockIdx.x * BM;
    const float* S = g_S + (size_t)bh * SEQ * SEQ;
    const float* V = g_qkv + (size_t)b * SEQ * QKVC + 2 * CH + h * HD;

    extern __shared__ float sm[];
    float* V3s  = sm;                            /* [64][132] */
    float* Ps   = V3s + BM * V3_STR;             /* [64][132] (Smid -> P tf32) */
    float* Vs   = Ps + BM * PS_STR;              /* [128][72] tf32 */
    float* resc = Vs + BJ * VS_STR;              /* [64] */
    float* sums = resc + BM;                     /* [64] */

    int tid = threadIdx.x;
    int warp = tid >> 5, lane = tid & 31, lr = lane >> 2, lc = lane & 3;
    int wm = (warp >> 1) * 16, wn = (warp & 1) * 32;
    int ib = tid >> 2, cc = tid & 3;            /* flash lane layout */

    float Mi = -INFINITY, sumi = 0.f;
    float acc[4][4] = {};

    for (int jt = 0; jt < SEQ / BJ; jt++) {
        int j0 = jt * BJ;
        /* stage A: vertical 3-sum + center row into smem */
        for (int idx = tid; idx < BM * (BJ + 2); idx += 256) {
            int i = idx / (BJ + 2), jj = idx % (BJ + 2);
            int gi = m0 + i, j = j0 + jj - 1;
            float v3 = 0.f, mid = 0.f;
            if (j >= 0 && j < SEQ) {
                const float* col = S + j;
                mid = col[(size_t)gi * SEQ];
                v3 = mid;
                if (gi > 0)       v3 += col[(size_t)(gi - 1) * SEQ];
                if (gi < SEQ - 1) v3 += col[(size_t)(gi + 1) * SEQ];
            }
            V3s[i * V3_STR + jj] = v3;
            if (jj >= 1 && jj <= BJ) Ps[i * PS_STR + jj - 1] = mid;
        }
        /* stage C: V tile -> smem (tf32, [k][n]) */
        for (int idx = tid; idx < BJ * (HD / 4); idx += 256) {
            int kr = idx >> 4, nc = (idx & 15) * 4;
            float4 v = *(const float4*)(V + (size_t)(j0 + kr) * QKVC + nc);
            float* dst = Vs + kr * VS_STR + nc;
            dst[0] = to_tf32(v.x); dst[1] = to_tf32(v.y);
            dst[2] = to_tf32(v.z); dst[3] = to_tf32(v.w);
        }
        __syncthreads();

        /* stage B: conv + online softmax, write P (tf32) */
        float Av[32];
        float tmax = -INFINITY;
        #pragma unroll
        for (int k = 0; k < 32; k++) {
            int jj = k * 4 + cc;
            float a = (1.0f + BETA) * Ps[ib * PS_STR + jj]
                    - BETA * (V3s[ib * V3_STR + jj] + V3s[ib * V3_STR + jj + 1]
                              + V3s[ib * V3_STR + jj + 2]);
            Av[k] = a;
            tmax = fmaxf(tmax, a);
        }
        tmax = fmaxf(tmax, __shfl_xor_sync(0xffffffffu, tmax, 1));
        tmax = fmaxf(tmax, __shfl_xor_sync(0xffffffffu, tmax, 2));
        float mnew = fmaxf(Mi, tmax);
        float scl = __expf(Mi - mnew);
        float ts = 0.f;
        #pragma unroll
        for (int k = 0; k < 32; k++) {
            float e = __expf(Av[k] - mnew);
            ts += e;
            Ps[ib * PS_STR + k * 4 + cc] = to_tf32(e);
        }
        ts += __shfl_xor_sync(0xffffffffu, ts, 1);
        ts += __shfl_xor_sync(0xffffffffu, ts, 2);
        sumi = sumi * scl + ts;
        Mi = mnew;
        if (cc == 0) {
            resc[ib] = scl;
            if (jt == SEQ / BJ - 1) sums[ib] = sumi;
        }
        __syncthreads();

        /* stage D: acc = acc*rescale + P @ V (tf32 MMA) */
        float rs0 = resc[wm + lr], rs1 = resc[wm + lr + 8];
        #pragma unroll
        for (int ni = 0; ni < 4; ni++) {
            acc[ni][0] *= rs0; acc[ni][1] *= rs0;
            acc[ni][2] *= rs1; acc[ni][3] *= rs1;
        }
        #pragma unroll
        for (int kb = 0; kb < BJ; kb += 8) {
            float a[4];
            a[0] = Ps[(wm + lr    ) * PS_STR + kb + lc];
            a[1] = Ps[(wm + lr + 8) * PS_STR + kb + lc];
            a[2] = Ps[(wm + lr    ) * PS_STR + kb + lc + 4];
            a[3] = Ps[(wm + lr + 8) * PS_STR + kb + lc + 4];
            #pragma unroll
            for (int ni = 0; ni < 4; ni++) {
                float bb[2];
                bb[0] = Vs[(kb + lc    ) * VS_STR + wn + ni * 8 + lr];
                bb[1] = Vs[(kb + lc + 4) * VS_STR + wn + ni * 8 + lr];
                mma8(acc[ni], a, bb);
            }
        }
        __syncthreads();
    }

    /* epilogue: normalize and write */
    float inv0 = 1.0f / sums[wm + lr];
    float inv1 = 1.0f / sums[wm + lr + 8];
    int r0 = m0 + wm + lr, r1 = r0 + 8;
    #pragma unroll
    for (int ni = 0; ni < 4; ni++) {
        int col = h * HD + wn + ni * 8 + lc * 2;
        out[((size_t)b * SEQ + r0) * CH + col    ] = acc[ni][0] * inv0;
        out[((size_t)b * SEQ + r0) * CH + col + 1] = acc[ni][1] * inv0;
        out[((size_t)b * SEQ + r1) * CH + col    ] = acc[ni][2] * inv1;
        out[((size_t)b * SEQ + r1) * CH + col + 1] = acc[ni][3] * inv1;
    }
}

#define FUSED_SMEM ((BM*V3_STR + BM*PS_STR + BJ*VS_STR + 2*BM) * (int)sizeof(float))

extern "C" void kernel_launch(void* const* d_in, const int* in_sizes, int n_in,
                              void* d_out, int out_size) {
    const float* x     = (const float*)d_in[0];
    const float* qkv_w = (const float*)d_in[1];
    const float* qkv_b = (const float*)d_in[2];
    const float* ln_g  = (const float*)d_in[3];
    const float* ln_b  = (const float*)d_in[4];
    float* out = (float*)d_out;

    cudaFuncSetAttribute(fused_tail, cudaFuncAttributeMaxDynamicSharedMemorySize,
                         FUSED_SMEM);

    ln_kernel<<<ROWS, 256>>>(x, ln_g, ln_b);
    qkv_gemm<<<dim3(QKVC / 64, ROWS / 128), 256>>>(qkv_w, qkv_b);
    score_gemm<<<dim3(SEQ / 64, SEQ / 128, BH), 256>>>();
    fused_tail<<<dim3(SEQ / BM, BH), 256, FUSED_SMEM>>>(out);
}

// round 5
// speedup vs baseline: 2.3236x; 2.3236x over previous
#include <cuda_runtime.h>
#include <math.h>

#define BN   4
#define SEQ  1024
#define CH   768
#define NH   12
#define HD   64
#define ROWS (BN*SEQ)
#define QKVC (3*CH)
#define BH   (BN*NH)
#define BETA 0.2f
#define SCALE 0.125f
#define LN_EPS 1e-5f

__device__ float g_xn[(size_t)ROWS * CH];
__device__ float g_qkv[(size_t)ROWS * QKVC];
__device__ float g_S[(size_t)BH * SEQ * SEQ];
__device__ float g_P[(size_t)BH * SEQ * SEQ];

__device__ __forceinline__ float to_tf32(float x) {
    unsigned u;
    asm("cvt.rna.tf32.f32 %0, %1;" : "=r"(u) : "f"(x));
    return __uint_as_float(u);
}
__device__ __forceinline__ void mma8(float* c, const float* a, const float* b) {
    asm volatile(
        "mma.sync.aligned.m16n8k8.row.col.f32.tf32.tf32.f32 "
        "{%0,%1,%2,%3}, {%4,%5,%6,%7}, {%8,%9}, {%0,%1,%2,%3};"
        : "+f"(c[0]), "+f"(c[1]), "+f"(c[2]), "+f"(c[3])
        : "r"(__float_as_uint(a[0])), "r"(__float_as_uint(a[1])),
          "r"(__float_as_uint(a[2])), "r"(__float_as_uint(a[3])),
          "r"(__float_as_uint(b[0])), "r"(__float_as_uint(b[1])));
}

/* ================= LayerNorm: one block per token ================= */
__global__ void ln_kernel(const float* __restrict__ x,
                          const float* __restrict__ gamma,
                          const float* __restrict__ beta) {
    int row = blockIdx.x;
    const float* xr = x + (size_t)row * CH;
    float*       orow = g_xn + (size_t)row * CH;
    int t = threadIdx.x;

    float v0 = xr[t], v1 = xr[t + 256], v2 = xr[t + 512];
    float s  = v0 + v1 + v2;
    float sq = v0 * v0 + v1 * v1 + v2 * v2;

    __shared__ float redS[8], redQ[8], stats[2];
    #pragma unroll
    for (int o = 16; o; o >>= 1) {
        s  += __shfl_down_sync(0xffffffffu, s,  o);
        sq += __shfl_down_sync(0xffffffffu, sq, o);
    }
    int w = t >> 5, l = t & 31;
    if (l == 0) { redS[w] = s; redQ[w] = sq; }
    __syncthreads();
    if (t == 0) {
        float S = 0.f, Q = 0.f;
        #pragma unroll
        for (int i = 0; i < 8; i++) { S += redS[i]; Q += redQ[i]; }
        float mu  = S * (1.0f / CH);
        float var = Q * (1.0f / CH) - mu * mu;
        stats[0] = mu;
        stats[1] = rsqrtf(var + LN_EPS);
    }
    __syncthreads();
    float mu = stats[0], rs = stats[1];
    orow[t]       = (v0 - mu) * rs * gamma[t]       + beta[t];
    orow[t + 256] = (v1 - mu) * rs * gamma[t + 256] + beta[t + 256];
    orow[t + 512] = (v2 - mu) * rs * gamma[t + 512] + beta[t + 512];
}

/* ========== QKV GEMM (tf32 MMA) ========== */
__global__ void qkv_gemm(const float* __restrict__ W,
                         const float* __restrict__ bias) {
    __shared__ float As[128][20];
    __shared__ float Bs[64][20];
    int m0 = blockIdx.y * 128, n0 = blockIdx.x * 64;
    int t = threadIdx.x;
    int warp = t >> 5, lane = t & 31, lr = lane >> 2, lc = lane & 3;
    int wm = (warp >> 1) * 32, wn = (warp & 1) * 32;
    int r = t >> 2, c4 = (t & 3) * 4;

    float acc[2][4][4] = {};
    for (int k0 = 0; k0 < CH; k0 += 16) {
        float4 a0 = *(const float4*)(g_xn + (size_t)(m0 + r) * CH + k0 + c4);
        float4 a1 = *(const float4*)(g_xn + (size_t)(m0 + r + 64) * CH + k0 + c4);
        float4 bb = *(const float4*)(W    + (size_t)(n0 + r) * CH + k0 + c4);
        As[r][c4+0]=to_tf32(a0.x); As[r][c4+1]=to_tf32(a0.y); As[r][c4+2]=to_tf32(a0.z); As[r][c4+3]=to_tf32(a0.w);
        As[r+64][c4+0]=to_tf32(a1.x); As[r+64][c4+1]=to_tf32(a1.y); As[r+64][c4+2]=to_tf32(a1.z); As[r+64][c4+3]=to_tf32(a1.w);
        Bs[r][c4+0]=to_tf32(bb.x); Bs[r][c4+1]=to_tf32(bb.y); Bs[r][c4+2]=to_tf32(bb.z); Bs[r][c4+3]=to_tf32(bb.w);
        __syncthreads();
        #pragma unroll
        for (int kc = 0; kc < 2; kc++) {
            int kb = kc * 8;
            float a[2][4], b[4][2];
            #pragma unroll
            for (int mi = 0; mi < 2; mi++) {
                a[mi][0] = As[wm + mi*16 + lr    ][kb + lc];
                a[mi][1] = As[wm + mi*16 + lr + 8][kb + lc];
                a[mi][2] = As[wm + mi*16 + lr    ][kb + lc + 4];
                a[mi][3] = As[wm + mi*16 + lr + 8][kb + lc + 4];
            }
            #pragma unroll
            for (int ni = 0; ni < 4; ni++) {
                b[ni][0] = Bs[wn + ni*8 + lr][kb + lc];
                b[ni][1] = Bs[wn + ni*8 + lr][kb + lc + 4];
            }
            #pragma unroll
            for (int mi = 0; mi < 2; mi++)
                #pragma unroll
                for (int ni = 0; ni < 4; ni++)
                    mma8(acc[mi][ni], a[mi], b[ni]);
        }
        __syncthreads();
    }
    #pragma unroll
    for (int mi = 0; mi < 2; mi++)
        #pragma unroll
        for (int ni = 0; ni < 4; ni++) {
            int row = m0 + wm + mi*16 + lr;
            int col = n0 + wn + ni*8 + lc*2;
            g_qkv[(size_t)row * QKVC + col    ] = acc[mi][ni][0] + bias[col];
            g_qkv[(size_t)row * QKVC + col + 1] = acc[mi][ni][1] + bias[col+1];
            g_qkv[(size_t)(row+8) * QKVC + col    ] = acc[mi][ni][2] + bias[col];
            g_qkv[(size_t)(row+8) * QKVC + col + 1] = acc[mi][ni][3] + bias[col+1];
        }
}

/* ========== Scores (tf32 MMA) ========== */
__global__ void score_gemm() {
    int bh = blockIdx.z, b = bh / NH, h = bh % NH;
    const float* Q = g_qkv + (size_t)b * SEQ * QKVC + h * HD;
    const float* K = g_qkv + (size_t)b * SEQ * QKVC + CH + h * HD;
    float* S = g_S + (size_t)bh * SEQ * SEQ;

    __shared__ float As[128][20];
    __shared__ float Bs[64][20];
    int m0 = blockIdx.y * 128, n0 = blockIdx.x * 64;
    int t = threadIdx.x;
    int warp = t >> 5, lane = t & 31, lr = lane >> 2, lc = lane & 3;
    int wm = (warp >> 1) * 32, wn = (warp & 1) * 32;
    int r = t >> 2, c4 = (t & 3) * 4;

    float acc[2][4][4] = {};
    for (int k0 = 0; k0 < HD; k0 += 16) {
        float4 a0 = *(const float4*)(Q + (size_t)(m0 + r) * QKVC + k0 + c4);
        float4 a1 = *(const float4*)(Q + (size_t)(m0 + r + 64) * QKVC + k0 + c4);
        float4 bb = *(const float4*)(K + (size_t)(n0 + r) * QKVC + k0 + c4);
        As[r][c4+0]=to_tf32(a0.x); As[r][c4+1]=to_tf32(a0.y); As[r][c4+2]=to_tf32(a0.z); As[r][c4+3]=to_tf32(a0.w);
        As[r+64][c4+0]=to_tf32(a1.x); As[r+64][c4+1]=to_tf32(a1.y); As[r+64][c4+2]=to_tf32(a1.z); As[r+64][c4+3]=to_tf32(a1.w);
        Bs[r][c4+0]=to_tf32(bb.x); Bs[r][c4+1]=to_tf32(bb.y); Bs[r][c4+2]=to_tf32(bb.z); Bs[r][c4+3]=to_tf32(bb.w);
        __syncthreads();
        #pragma unroll
        for (int kc = 0; kc < 2; kc++) {
            int kb = kc * 8;
            float a[2][4], b[4][2];
            #pragma unroll
            for (int mi = 0; mi < 2; mi++) {
                a[mi][0] = As[wm + mi*16 + lr    ][kb + lc];
                a[mi][1] = As[wm + mi*16 + lr + 8][kb + lc];
                a[mi][2] = As[wm + mi*16 + lr    ][kb + lc + 4];
                a[mi][3] = As[wm + mi*16 + lr + 8][kb + lc + 4];
            }
            #pragma unroll
            for (int ni = 0; ni < 4; ni++) {
                b[ni][0] = Bs[wn + ni*8 + lr][kb + lc];
                b[ni][1] = Bs[wn + ni*8 + lr][kb + lc + 4];
            }
            #pragma unroll
            for (int mi = 0; mi < 2; mi++)
                #pragma unroll
                for (int ni = 0; ni < 4; ni++)
                    mma8(acc[mi][ni], a[mi], b[ni]);
        }
        __syncthreads();
    }
    #pragma unroll
    for (int mi = 0; mi < 2; mi++)
        #pragma unroll
        for (int ni = 0; ni < 4; ni++) {
            int row = m0 + wm + mi*16 + lr;
            int col = n0 + wn + ni*8 + lc*2;
            S[(size_t)row * SEQ + col    ] = acc[mi][ni][0] * SCALE;
            S[(size_t)row * SEQ + col + 1] = acc[mi][ni][1] * SCALE;
            S[(size_t)(row+8) * SEQ + col    ] = acc[mi][ni][2] * SCALE;
            S[(size_t)(row+8) * SEQ + col + 1] = acc[mi][ni][3] * SCALE;
        }
}

/* ============ Lateral inhibition conv + row softmax (v2) ============ */
/* Block = 4 output rows of one (b,h). 6 raw S rows staged in smem,    */
/* vertical 3-sum vectorized, horizontal neighbors via warp shuffle.   */
#define CR 4
__global__ __launch_bounds__(256) void conv_softmax_v2() {
    int bh = blockIdx.y;
    int i0 = blockIdx.x * CR;
    const float* S = g_S + (size_t)bh * SEQ * SEQ;
    float*       P = g_P + (size_t)bh * SEQ * SEQ;

    __shared__ float rows[6][SEQ];
    __shared__ float red[CR][8];
    __shared__ float bc[CR];

    int t = threadIdx.x, lane = t & 31, w = t >> 5;
    int j0 = t * 4;

    /* stage 6 rows i0-1 .. i0+4 (zero pad at edges) */
    #pragma unroll
    for (int r = 0; r < 6; r++) {
        int gi = i0 - 1 + r;
        float4 v = make_float4(0.f, 0.f, 0.f, 0.f);
        if (gi >= 0 && gi < SEQ) v = *(const float4*)(S + (size_t)gi * SEQ + j0);
        *(float4*)&rows[r][j0] = v;
    }
    __syncthreads();

    float a[CR][4], mx[CR];
    #pragma unroll
    for (int r = 0; r < CR; r++) {
        float4 x = *(const float4*)&rows[r    ][j0];
        float4 y = *(const float4*)&rows[r + 1][j0];
        float4 z = *(const float4*)&rows[r + 2][j0];
        float4 vs;  /* vertical 3-sums for j0..j0+3 */
        vs.x = x.x + y.x + z.x;  vs.y = x.y + y.y + z.y;
        vs.z = x.z + y.z + z.z;  vs.w = x.w + y.w + z.w;

        float left  = __shfl_up_sync(0xffffffffu, vs.w, 1);
        float right = __shfl_down_sync(0xffffffffu, vs.x, 1);
        if (lane == 0) {   /* j0-1 crosses warp boundary */
            int j = j0 - 1;
            left = (j >= 0) ? rows[r][j] + rows[r + 1][j] + rows[r + 2][j] : 0.f;
        }
        if (lane == 31) {  /* j0+4 crosses warp boundary */
            int j = j0 + 4;
            right = (j < SEQ) ? rows[r][j] + rows[r + 1][j] + rows[r + 2][j] : 0.f;
        }

        a[r][0] = (1.0f + BETA) * y.x - BETA * (left + vs.x + vs.y);
        a[r][1] = (1.0f + BETA) * y.y - BETA * (vs.x + vs.y + vs.z);
        a[r][2] = (1.0f + BETA) * y.z - BETA * (vs.y + vs.z + vs.w);
        a[r][3] = (1.0f + BETA) * y.w - BETA * (vs.z + vs.w + right);
        mx[r] = fmaxf(fmaxf(a[r][0], a[r][1]), fmaxf(a[r][2], a[r][3]));
    }

    /* block max per row */
    #pragma unroll
    for (int r = 0; r < CR; r++) {
        float m = mx[r];
        #pragma unroll
        for (int o = 16; o; o >>= 1) m = fmaxf(m, __shfl_xor_sync(0xffffffffu, m, o));
        if (lane == 0) red[r][w] = m;
    }
    __syncthreads();
    if (t < CR) {
        float m = red[t][0];
        #pragma unroll
        for (int k = 1; k < 8; k++) m = fmaxf(m, red[t][k]);
        bc[t] = m;
    }
    __syncthreads();

    float sm[CR];
    #pragma unroll
    for (int r = 0; r < CR; r++) {
        float M = bc[r];
        float s = 0.f;
        #pragma unroll
        for (int q = 0; q < 4; q++) { a[r][q] = __expf(a[r][q] - M); s += a[r][q]; }
        sm[r] = s;
    }
    __syncthreads();   /* reuse red/bc */
    #pragma unroll
    for (int r = 0; r < CR; r++) {
        float s = sm[r];
        #pragma unroll
        for (int o = 16; o; o >>= 1) s += __shfl_xor_sync(0xffffffffu, s, o);
        if (lane == 0) red[r][w] = s;
    }
    __syncthreads();
    if (t < CR) {
        float s = 0.f;
        #pragma unroll
        for (int k = 0; k < 8; k++) s += red[t][k];
        bc[t] = 1.0f / s;
    }
    __syncthreads();

    #pragma unroll
    for (int r = 0; r < CR; r++) {
        float inv = bc[r];
        float4 o;
        o.x = a[r][0] * inv; o.y = a[r][1] * inv;
        o.z = a[r][2] * inv; o.w = a[r][3] * inv;
        *(float4*)(P + (size_t)(i0 + r) * SEQ + j0) = o;
    }
}

/* ========== PV GEMM (tf32 MMA): out = P @ V ========== */
__global__ void pv_gemm(float* __restrict__ out) {
    int bh = blockIdx.y, b = bh / NH, h = bh % NH;
    const float* P = g_P + (size_t)bh * SEQ * SEQ;
    const float* V = g_qkv + (size_t)b * SEQ * QKVC + 2 * CH + h * HD;
    int m0 = blockIdx.x * 128;

    __shared__ float As[128][20];
    __shared__ float Vs[16][72];
    int t = threadIdx.x;
    int warp = t >> 5, lane = t & 31, lr = lane >> 2, lc = lane & 3;
    int wm = (warp >> 1) * 32, wn = (warp & 1) * 32;
    int r = t >> 2, c4 = (t & 3) * 4;
    int kr = t >> 4, vc4 = (t & 15) * 4;

    float acc[2][4][4] = {};
    for (int k0 = 0; k0 < SEQ; k0 += 16) {
        float4 a0 = *(const float4*)(P + (size_t)(m0 + r) * SEQ + k0 + c4);
        float4 a1 = *(const float4*)(P + (size_t)(m0 + r + 64) * SEQ + k0 + c4);
        float4 v  = *(const float4*)(V + (size_t)(k0 + kr) * QKVC + vc4);
        As[r][c4+0]=to_tf32(a0.x); As[r][c4+1]=to_tf32(a0.y); As[r][c4+2]=to_tf32(a0.z); As[r][c4+3]=to_tf32(a0.w);
        As[r+64][c4+0]=to_tf32(a1.x); As[r+64][c4+1]=to_tf32(a1.y); As[r+64][c4+2]=to_tf32(a1.z); As[r+64][c4+3]=to_tf32(a1.w);
        Vs[kr][vc4+0]=to_tf32(v.x); Vs[kr][vc4+1]=to_tf32(v.y); Vs[kr][vc4+2]=to_tf32(v.z); Vs[kr][vc4+3]=to_tf32(v.w);
        __syncthreads();
        #pragma unroll
        for (int kc = 0; kc < 2; kc++) {
            int kb = kc * 8;
            float a[2][4], bfr[4][2];
            #pragma unroll
            for (int mi = 0; mi < 2; mi++) {
                a[mi][0] = As[wm + mi*16 + lr    ][kb + lc];
                a[mi][1] = As[wm + mi*16 + lr + 8][kb + lc];
                a[mi][2] = As[wm + mi*16 + lr    ][kb + lc + 4];
                a[mi][3] = As[wm + mi*16 + lr + 8][kb + lc + 4];
            }
            #pragma unroll
            for (int ni = 0; ni < 4; ni++) {
                bfr[ni][0] = Vs[kb + lc    ][wn + ni*8 + lr];
                bfr[ni][1] = Vs[kb + lc + 4][wn + ni*8 + lr];
            }
            #pragma unroll
            for (int mi = 0; mi < 2; mi++)
                #pragma unroll
                for (int ni = 0; ni < 4; ni++)
                    mma8(acc[mi][ni], a[mi], bfr[ni]);
        }
        __syncthreads();
    }
    #pragma unroll
    for (int mi = 0; mi < 2; mi++)
        #pragma unroll
        for (int ni = 0; ni < 4; ni++) {
            int row = m0 + wm + mi*16 + lr;
            int col = wn + ni*8 + lc*2;
            out[((size_t)b * SEQ + row) * CH + h*HD + col    ] = acc[mi][ni][0];
            out[((size_t)b * SEQ + row) * CH + h*HD + col + 1] = acc[mi][ni][1];
            out[((size_t)b * SEQ + row + 8) * CH + h*HD + col    ] = acc[mi][ni][2];
            out[((size_t)b * SEQ + row + 8) * CH + h*HD + col + 1] = acc[mi][ni][3];
        }
}

extern "C" void kernel_launch(void* const* d_in, const int* in_sizes, int n_in,
                              void* d_out, int out_size) {
    const float* x     = (const float*)d_in[0];
    const float* qkv_w = (const float*)d_in[1];
    const float* qkv_b = (const float*)d_in[2];
    const float* ln_g  = (const float*)d_in[3];
    const float* ln_b  = (const float*)d_in[4];
    float* out = (float*)d_out;

    ln_kernel<<<ROWS, 256>>>(x, ln_g, ln_b);
    qkv_gemm<<<dim3(QKVC / 64, ROWS / 128), 256>>>(qkv_w, qkv_b);
    score_gemm<<<dim3(SEQ / 64, SEQ / 128, BH), 256>>>();
    conv_softmax_v2<<<dim3(SEQ / CR, BH), 256>>>();
    pv_gemm<<<dim3(SEQ / 128, BH), 256>>>(out);
}